// round 10
// baseline (speedup 1.0000x reference)
#include <cuda_runtime.h>
#include <cuda_bf16.h>
#include <cstdint>

// Shapes (fixed by reference setup_inputs)
#define NROWS 16384   // B*L
#define DDIM  512
#define DC    16
#define KCB   8192
#define LN_EPS 1e-5f

// ---------------- device scratch (no allocation allowed) --------------------
// 3-way bf16 splits of NEGATED LN(h) and of codebook; fp32 half-norms.
__device__ __nv_bfloat16 g_h1[NROWS * DC], g_h2[NROWS * DC], g_h3[NROWS * DC];
__device__ __nv_bfloat16 g_c1[KCB * DC],   g_c2[KCB * DC],   g_c3[KCB * DC];
__device__ float         g_hc2[KCB];       // 0.5 * sum c^2

// ---------------- helpers ---------------------------------------------------
__device__ __forceinline__ void split3(float v, __nv_bfloat16& s1,
                                       __nv_bfloat16& s2, __nv_bfloat16& s3) {
    s1 = __float2bfloat16(v);
    float r = v - __bfloat162float(s1);
    s2 = __float2bfloat16(r);
    float r2 = r - __bfloat162float(s2);
    s3 = __float2bfloat16(r2);
}

__device__ __forceinline__ uint32_t pack_bf2(__nv_bfloat16 lo, __nv_bfloat16 hi) {
    uint16_t a = __bfloat16_as_ushort(lo), b = __bfloat16_as_ushort(hi);
    return (uint32_t)a | ((uint32_t)b << 16);
}

__device__ __forceinline__ void mma_bf16(float& d0, float& d1, float& d2, float& d3,
                                         uint32_t a0, uint32_t a1, uint32_t a2, uint32_t a3,
                                         uint32_t b0, uint32_t b1) {
    asm volatile(
        "mma.sync.aligned.m16n8k16.row.col.f32.bf16.bf16.f32 "
        "{%0,%1,%2,%3}, {%4,%5,%6,%7}, {%8,%9}, {%0,%1,%2,%3};"
        : "+f"(d0), "+f"(d1), "+f"(d2), "+f"(d3)
        : "r"(a0), "r"(a1), "r"(a2), "r"(a3), "r"(b0), "r"(b1));
}

__device__ __forceinline__ void ldsm_x2(uint32_t& r0, uint32_t& r1, uint32_t saddr) {
    asm volatile("ldmatrix.sync.aligned.m8n8.x2.shared.b16 {%0,%1}, [%2];"
                 : "=r"(r0), "=r"(r1) : "r"(saddr));
}

// ---------------- kernel 0: codebook prep (splits + half-norms) -------------
__global__ void k_prep(const float* __restrict__ cb) {
    int k = blockIdx.x * blockDim.x + threadIdx.x;
    if (k >= KCB) return;
    const float* c = cb + (size_t)k * DC;
    float c2 = 0.f;
#pragma unroll
    for (int j = 0; j < DC; j++) c2 = fmaf(c[j], c[j], c2);
    g_hc2[k] = 0.5f * c2;
#pragma unroll
    for (int j = 0; j < DC; j++) {
        __nv_bfloat16 s1, s2, s3;
        split3(c[j], s1, s2, s3);
        g_c1[k * DC + j] = s1; g_c2[k * DC + j] = s2; g_c3[k * DC + j] = s3;
    }
}

// ---------------- kernel 1: projection + LayerNorm -> split(-h) -------------
// One warp per 4 rows; 8 warps/block; 512 blocks. (R8 math, unchanged.)
__global__ void __launch_bounds__(256) k_proj(
    const float* __restrict__ x, const float* __restrict__ W)
{
    const int warp = threadIdx.x >> 5;
    const int lane = threadIdx.x & 31;
    const int rowBase = (blockIdx.x * 8 + warp) * 4;

#pragma unroll
    for (int r = 0; r < 4; r++) {
        const int row = rowBase + r;
        float acc[DC];
#pragma unroll
        for (int j = 0; j < DC; j++) acc[j] = 0.f;

        const float* xrow = x + (size_t)row * DDIM;
#pragma unroll 4
        for (int d = lane; d < DDIM; d += 32) {
            float xv = xrow[d];
#pragma unroll
            for (int j = 0; j < DC; j++)
                acc[j] = fmaf(xv, W[j * DDIM + d], acc[j]);
        }
#pragma unroll
        for (int j = 0; j < DC; j++) {
#pragma unroll
            for (int ofs = 16; ofs > 0; ofs >>= 1)
                acc[j] += __shfl_xor_sync(0xFFFFFFFFu, acc[j], ofs);
        }

        float s = 0.f;
#pragma unroll
        for (int j = 0; j < DC; j++) s += acc[j];
        float mu = s * (1.0f / DC);
        float v = 0.f;
#pragma unroll
        for (int j = 0; j < DC; j++) { float d = acc[j] - mu; v = fmaf(d, d, v); }
        float denom = sqrtf(v * (1.0f / DC) + LN_EPS);

        // negated normalized h, split 3-way, lanes 0..7 write bf16x2 pairs
        if (lane < 8) {
            float e0 = (mu - acc[2 * lane]) / denom;
            float e1 = (mu - acc[2 * lane + 1]) / denom;
            __nv_bfloat16 a1, a2, a3, b1, b2, b3;
            split3(e0, a1, a2, a3);
            split3(e1, b1, b2, b3);
            ((uint32_t*)&g_h1[row * DC])[lane] = pack_bf2(a1, b1);
            ((uint32_t*)&g_h2[row * DC])[lane] = pack_bf2(a2, b2);
            ((uint32_t*)&g_h3[row * DC])[lane] = pack_bf2(a3, b3);
        }
    }
}

// ---------------- kernel 2: tensor-core distance + argmin -------------------
// 128 blocks x 256 threads. Block = 128-row tile; warp w owns rows w*16..+15.
// Codes stream through double-buffered smem in 128-code chunks.
#define CHUNK 128
__global__ void __launch_bounds__(256) k_dist(float* __restrict__ out) {
    __shared__ __nv_bfloat16 smC[2][3][CHUNK * DC];  // 2 x 3 x 4KB
    __shared__ float         smH[2][CHUNK];          // 2 x 512B

    const int tid  = threadIdx.x;
    const int warp = tid >> 5;
    const int lane = tid & 31;
    const int row0 = blockIdx.x * 128 + warp * 16;
    const int r4   = lane >> 2;        // 0..7  (row within 8-group)
    const int kp   = (lane & 3) * 2;   // 0,2,4,6 (k-pair / col-pair offset)

    // ---- loop-invariant A fragments: this warp's 16 rows, 3 splits ----
    uint32_t a[3][4];
    {
        const __nv_bfloat16* hs[3] = {g_h1, g_h2, g_h3};
#pragma unroll
        for (int s = 0; s < 3; s++) {
            a[s][0] = *(const uint32_t*)&hs[s][(row0 + r4) * DC + kp];
            a[s][1] = *(const uint32_t*)&hs[s][(row0 + 8 + r4) * DC + kp];
            a[s][2] = *(const uint32_t*)&hs[s][(row0 + r4) * DC + kp + 8];
            a[s][3] = *(const uint32_t*)&hs[s][(row0 + 8 + r4) * DC + kp + 8];
        }
    }

    // staging helper (uint4 copies; 256 uint4 per 4KB split)
    auto stage = [&](int ch, int buf) {
        const __nv_bfloat16* srcs[3] = {g_c1, g_c2, g_c3};
#pragma unroll
        for (int s = 0; s < 3; s++) {
            ((uint4*)smC[buf][s])[tid] =
                ((const uint4*)(srcs[s] + (size_t)ch * CHUNK * DC))[tid];
        }
        if (tid < CHUNK * 4 / 16)  // 32 uint4 = 512B of hc2
            ((uint4*)smH[buf])[tid] = ((const uint4*)(g_hc2 + ch * CHUNK))[tid];
    };

    float bv[4] = {3.4e38f, 3.4e38f, 3.4e38f, 3.4e38f};
    int   bn[4] = {0, 0, 0, 0};     // chunk-base code index per slot

    // ldmatrix row address lane mapping (threads 0..15 supply addresses)
    const int lm = lane & 15;
    const int lrow = lm & 7;         // code row within n8
    const int lcol = (lm >> 3) * 8;  // k-half: 0 or 8

    stage(0, 0);
    __syncthreads();

    for (int ch = 0; ch < KCB / CHUNK; ch++) {
        const int buf = ch & 1;
        if (ch + 1 < KCB / CHUNK) stage(ch + 1, buf ^ 1);

        uint32_t sb[3];
#pragma unroll
        for (int s = 0; s < 3; s++)
            sb[s] = (uint32_t)__cvta_generic_to_shared(&smC[buf][s][0]);

#pragma unroll 2
        for (int no = 0; no < CHUNK; no += 8) {
            // B fragments for the 3 splits
            uint32_t b[3][2];
#pragma unroll
            for (int s = 0; s < 3; s++)
                ldsm_x2(b[s][0], b[s][1],
                        sb[s] + (uint32_t)(((no + lrow) * DC + lcol) * 2));

            // D init = 0.5*||c||^2 for this thread's two columns
            float2 hh = *(const float2*)&smH[buf][no + kp];
            float d0 = hh.x, d1 = hh.y, d2 = hh.x, d3 = hh.y;

            // 6-term split MMA: exact to ~2^-24
            mma_bf16(d0, d1, d2, d3, a[0][0], a[0][1], a[0][2], a[0][3], b[0][0], b[0][1]);
            mma_bf16(d0, d1, d2, d3, a[0][0], a[0][1], a[0][2], a[0][3], b[1][0], b[1][1]);
            mma_bf16(d0, d1, d2, d3, a[1][0], a[1][1], a[1][2], a[1][3], b[0][0], b[0][1]);
            mma_bf16(d0, d1, d2, d3, a[1][0], a[1][1], a[1][2], a[1][3], b[1][0], b[1][1]);
            mma_bf16(d0, d1, d2, d3, a[0][0], a[0][1], a[0][2], a[0][3], b[2][0], b[2][1]);
            mma_bf16(d0, d1, d2, d3, a[2][0], a[2][1], a[2][2], a[2][3], b[0][0], b[0][1]);

            // argmin update (ascending chunk order, strict < = first-min)
            const int nb = ch * CHUNK + no;
            if (d0 < bv[0]) { bv[0] = d0; bn[0] = nb; }
            if (d1 < bv[1]) { bv[1] = d1; bn[1] = nb; }
            if (d2 < bv[2]) { bv[2] = d2; bn[2] = nb; }
            if (d3 < bv[3]) { bv[3] = d3; bn[3] = nb; }
        }
        __syncthreads();
    }

    // ---- finalize: slot -> (value, global index), merge cols then quads ----
    // slots: 0:(rowA,col kp) 1:(rowA,kp+1) 2:(rowB,kp) 3:(rowB,kp+1)
    float vA = bv[0]; int iA = bn[0] + kp;
    {   float v = bv[1]; int i = bn[1] + kp + 1;
        if (v < vA || (v == vA && i < iA)) { vA = v; iA = i; } }
    float vB = bv[2]; int iB = bn[2] + kp;
    {   float v = bv[3]; int i = bn[3] + kp + 1;
        if (v < vB || (v == vB && i < iB)) { vB = v; iB = i; } }

#pragma unroll
    for (int ofs = 1; ofs <= 2; ofs <<= 1) {
        float v = __shfl_xor_sync(0xFFFFFFFFu, vA, ofs);
        int   i = __shfl_xor_sync(0xFFFFFFFFu, iA, ofs);
        if (v < vA || (v == vA && i < iA)) { vA = v; iA = i; }
        v = __shfl_xor_sync(0xFFFFFFFFu, vB, ofs);
        i = __shfl_xor_sync(0xFFFFFFFFu, iB, ofs);
        if (v < vB || (v == vB && i < iB)) { vB = v; iB = i; }
    }

    if ((lane & 3) == 0) {
        out[row0 + r4]     = (float)iA;
        out[row0 + 8 + r4] = (float)iB;
    }
}

// ---------------- launch -----------------------------------------------------
extern "C" void kernel_launch(void* const* d_in, const int* in_sizes, int n_in,
                              void* d_out, int out_size) {
    // Rank inputs by size: x (8388608) > codebook (131072) > proj_weight (8192)
    int a = 0, b = 1, c = 2;
    if (n_in >= 3) {
        if (in_sizes[a] < in_sizes[b]) { int t = a; a = b; b = t; }
        if (in_sizes[b] < in_sizes[c]) { int t = b; b = c; c = t; }
        if (in_sizes[a] < in_sizes[b]) { int t = a; a = b; b = t; }
    }
    const float* x  = (const float*)d_in[a];
    const float* cb = (const float*)d_in[b];
    const float* W  = (const float*)d_in[c];
    float* out = (float*)d_out;

    k_prep<<<KCB / 256, 256>>>(cb);
    k_proj<<<NROWS / 32, 256>>>(x, W);
    k_dist<<<NROWS / 128, 256>>>(out);
}

// round 11
// speedup vs baseline: 1.2011x; 1.2011x over previous
#include <cuda_runtime.h>
#include <cuda_bf16.h>
#include <cstdint>

// Shapes (fixed by reference setup_inputs)
#define NROWS 16384
#define DDIM  512
#define DC    16
#define KCB   8192
#define LN_EPS 1e-5f

// ---------------- device scratch (no allocation allowed) --------------------
__device__ __nv_bfloat16 g_h1[NROWS * DC], g_h2[NROWS * DC], g_h3[NROWS * DC];
__device__ __nv_bfloat16 g_c1[KCB * DC],   g_c2[KCB * DC],   g_c3[KCB * DC];
__device__ float         g_hc2[KCB];       // 0.5 * sum c^2

// ---------------- helpers ---------------------------------------------------
__device__ __forceinline__ void split3(float v, __nv_bfloat16& s1,
                                       __nv_bfloat16& s2, __nv_bfloat16& s3) {
    s1 = __float2bfloat16(v);
    float r = v - __bfloat162float(s1);
    s2 = __float2bfloat16(r);
    float r2 = r - __bfloat162float(s2);
    s3 = __float2bfloat16(r2);
}

__device__ __forceinline__ uint32_t pack_bf2(__nv_bfloat16 lo, __nv_bfloat16 hi) {
    uint16_t a = __bfloat16_as_ushort(lo), b = __bfloat16_as_ushort(hi);
    return (uint32_t)a | ((uint32_t)b << 16);
}

__device__ __forceinline__ void mma_bf16(float& d0, float& d1, float& d2, float& d3,
                                         uint32_t a0, uint32_t a1, uint32_t a2, uint32_t a3,
                                         uint32_t b0, uint32_t b1) {
    asm volatile(
        "mma.sync.aligned.m16n8k16.row.col.f32.bf16.bf16.f32 "
        "{%0,%1,%2,%3}, {%4,%5,%6,%7}, {%8,%9}, {%0,%1,%2,%3};"
        : "+f"(d0), "+f"(d1), "+f"(d2), "+f"(d3)
        : "r"(a0), "r"(a1), "r"(a2), "r"(a3), "r"(b0), "r"(b1));
}

__device__ __forceinline__ void ldsm_x4(uint32_t& r0, uint32_t& r1,
                                        uint32_t& r2, uint32_t& r3, uint32_t saddr) {
    asm volatile("ldmatrix.sync.aligned.m8n8.x4.shared.b16 {%0,%1,%2,%3}, [%4];"
                 : "=r"(r0), "=r"(r1), "=r"(r2), "=r"(r3) : "r"(saddr));
}

// ---------------- kernel 0: codebook prep (vectorized) ----------------------
__global__ void __launch_bounds__(128) k_prep(const float* __restrict__ cb) {
    int k = blockIdx.x * blockDim.x + threadIdx.x;
    if (k >= KCB) return;
    const float4* c4 = (const float4*)(cb + (size_t)k * DC);
    float4 q0 = c4[0], q1 = c4[1], q2 = c4[2], q3 = c4[3];
    float cv[DC] = {q0.x, q0.y, q0.z, q0.w, q1.x, q1.y, q1.z, q1.w,
                    q2.x, q2.y, q2.z, q2.w, q3.x, q3.y, q3.z, q3.w};
    float c2 = 0.f;
#pragma unroll
    for (int j = 0; j < DC; j++) c2 = fmaf(cv[j], cv[j], c2);
    g_hc2[k] = 0.5f * c2;

    uint32_t p1[8], p2[8], p3[8];
#pragma unroll
    for (int j = 0; j < 8; j++) {
        __nv_bfloat16 a1, a2, a3, b1, b2, b3;
        split3(cv[2 * j], a1, a2, a3);
        split3(cv[2 * j + 1], b1, b2, b3);
        p1[j] = pack_bf2(a1, b1); p2[j] = pack_bf2(a2, b2); p3[j] = pack_bf2(a3, b3);
    }
    ((uint4*)&g_c1[k * DC])[0] = *(uint4*)&p1[0];
    ((uint4*)&g_c1[k * DC])[1] = *(uint4*)&p1[4];
    ((uint4*)&g_c2[k * DC])[0] = *(uint4*)&p2[0];
    ((uint4*)&g_c2[k * DC])[1] = *(uint4*)&p2[4];
    ((uint4*)&g_c3[k * DC])[0] = *(uint4*)&p3[0];
    ((uint4*)&g_c3[k * DC])[1] = *(uint4*)&p3[4];
}

// ---------------- kernel 1: projection + LayerNorm -> split(-h) -------------
__global__ void __launch_bounds__(256) k_proj(
    const float* __restrict__ x, const float* __restrict__ W)
{
    const int warp = threadIdx.x >> 5;
    const int lane = threadIdx.x & 31;
    const int rowBase = (blockIdx.x * 8 + warp) * 4;

#pragma unroll
    for (int r = 0; r < 4; r++) {
        const int row = rowBase + r;
        float acc[DC];
#pragma unroll
        for (int j = 0; j < DC; j++) acc[j] = 0.f;

        const float* xrow = x + (size_t)row * DDIM;
#pragma unroll 4
        for (int d = lane; d < DDIM; d += 32) {
            float xv = xrow[d];
#pragma unroll
            for (int j = 0; j < DC; j++)
                acc[j] = fmaf(xv, W[j * DDIM + d], acc[j]);
        }
#pragma unroll
        for (int j = 0; j < DC; j++) {
#pragma unroll
            for (int ofs = 16; ofs > 0; ofs >>= 1)
                acc[j] += __shfl_xor_sync(0xFFFFFFFFu, acc[j], ofs);
        }

        float s = 0.f;
#pragma unroll
        for (int j = 0; j < DC; j++) s += acc[j];
        float mu = s * (1.0f / DC);
        float v = 0.f;
#pragma unroll
        for (int j = 0; j < DC; j++) { float d = acc[j] - mu; v = fmaf(d, d, v); }
        float denom = sqrtf(v * (1.0f / DC) + LN_EPS);

        if (lane < 8) {
            float e0 = (mu - acc[2 * lane]) / denom;
            float e1 = (mu - acc[2 * lane + 1]) / denom;
            __nv_bfloat16 a1, a2, a3, b1, b2, b3;
            split3(e0, a1, a2, a3);
            split3(e1, b1, b2, b3);
            ((uint32_t*)&g_h1[row * DC])[lane] = pack_bf2(a1, b1);
            ((uint32_t*)&g_h2[row * DC])[lane] = pack_bf2(a2, b2);
            ((uint32_t*)&g_h3[row * DC])[lane] = pack_bf2(a3, b3);
        }
    }
}

// ---------------- kernel 2: tensor-core distance + argmin -------------------
// 256 blocks x 128 threads (4 warps). Warp owns 16 rows. 16 codes / iteration
// via ldmatrix.x4; 12 MMAs in 4 independent 3-deep chains.
#define CHUNK 128
__global__ void __launch_bounds__(128) k_dist(float* __restrict__ out) {
    __shared__ __nv_bfloat16 smC[2][3][CHUNK * DC];  // 24 KB
    __shared__ float         smH[2][CHUNK];          // 1 KB

    const int tid  = threadIdx.x;
    const int warp = tid >> 5;
    const int lane = tid & 31;
    const int row0 = blockIdx.x * 64 + warp * 16;
    const int r4   = lane >> 2;
    const int kp   = (lane & 3) * 2;

    // loop-invariant A fragments (validated layout from R10)
    uint32_t a[3][4];
    {
        const __nv_bfloat16* hs[3] = {g_h1, g_h2, g_h3};
#pragma unroll
        for (int s = 0; s < 3; s++) {
            a[s][0] = *(const uint32_t*)&hs[s][(row0 + r4) * DC + kp];
            a[s][1] = *(const uint32_t*)&hs[s][(row0 + 8 + r4) * DC + kp];
            a[s][2] = *(const uint32_t*)&hs[s][(row0 + r4) * DC + kp + 8];
            a[s][3] = *(const uint32_t*)&hs[s][(row0 + 8 + r4) * DC + kp + 8];
        }
    }

    auto stage = [&](int ch, int buf) {
        const __nv_bfloat16* srcs[3] = {g_c1, g_c2, g_c3};
#pragma unroll
        for (int s = 0; s < 3; s++) {
            ((uint4*)smC[buf][s])[tid]       = ((const uint4*)(srcs[s] + (size_t)ch * CHUNK * DC))[tid];
            ((uint4*)smC[buf][s])[tid + 128] = ((const uint4*)(srcs[s] + (size_t)ch * CHUNK * DC))[tid + 128];
        }
        if (tid < 32) ((uint4*)smH[buf])[tid] = ((const uint4*)(g_hc2 + ch * CHUNK))[tid];
    };

    // ldmatrix.x4 lane mapping: two n8 blocks x two k-halves
    const int coderow = (lane & 7) + ((lane & 16) >> 1);  // 0..15
    const int khalf   = (lane >> 3) & 1;
    const uint32_t lmoff = (uint32_t)(coderow * 32 + khalf * 16);  // bytes

    float bv[8];
    int   bn[8];
#pragma unroll
    for (int s = 0; s < 8; s++) { bv[s] = 3.4e38f; bn[s] = 0; }

    stage(0, 0);
    __syncthreads();

    for (int ch = 0; ch < KCB / CHUNK; ch++) {
        const int buf = ch & 1;
        if (ch + 1 < KCB / CHUNK) stage(ch + 1, buf ^ 1);

        uint32_t sb[3];
#pragma unroll
        for (int s = 0; s < 3; s++)
            sb[s] = (uint32_t)__cvta_generic_to_shared(&smC[buf][s][0]) + lmoff;

#pragma unroll 2
        for (int no = 0; no < CHUNK; no += 16) {
            uint32_t b1[4], b2[4], b3[4];
            ldsm_x4(b1[0], b1[1], b1[2], b1[3], sb[0] + no * 32);
            ldsm_x4(b2[0], b2[1], b2[2], b2[3], sb[1] + no * 32);
            ldsm_x4(b3[0], b3[1], b3[2], b3[3], sb[2] + no * 32);

            float2 h0 = *(const float2*)&smH[buf][no + kp];
            float2 h1 = *(const float2*)&smH[buf][no + 8 + kp];

            // block0: P chain (seeded hc2) + Q chain (seeded 0); block1 same.
            float P0a = h0.x, P0b = h0.y, P0c = h0.x, P0d = h0.y;
            float Q0a = 0, Q0b = 0, Q0c = 0, Q0d = 0;
            float P1a = h1.x, P1b = h1.y, P1c = h1.x, P1d = h1.y;
            float Q1a = 0, Q1b = 0, Q1c = 0, Q1d = 0;

            mma_bf16(P0a,P0b,P0c,P0d, a[0][0],a[0][1],a[0][2],a[0][3], b1[0],b1[1]);
            mma_bf16(Q0a,Q0b,Q0c,Q0d, a[1][0],a[1][1],a[1][2],a[1][3], b1[0],b1[1]);
            mma_bf16(P1a,P1b,P1c,P1d, a[0][0],a[0][1],a[0][2],a[0][3], b1[2],b1[3]);
            mma_bf16(Q1a,Q1b,Q1c,Q1d, a[1][0],a[1][1],a[1][2],a[1][3], b1[2],b1[3]);
            mma_bf16(P0a,P0b,P0c,P0d, a[0][0],a[0][1],a[0][2],a[0][3], b2[0],b2[1]);
            mma_bf16(Q0a,Q0b,Q0c,Q0d, a[1][0],a[1][1],a[1][2],a[1][3], b2[0],b2[1]);
            mma_bf16(P1a,P1b,P1c,P1d, a[0][0],a[0][1],a[0][2],a[0][3], b2[2],b2[3]);
            mma_bf16(Q1a,Q1b,Q1c,Q1d, a[1][0],a[1][1],a[1][2],a[1][3], b2[2],b2[3]);
            mma_bf16(P0a,P0b,P0c,P0d, a[0][0],a[0][1],a[0][2],a[0][3], b3[0],b3[1]);
            mma_bf16(Q0a,Q0b,Q0c,Q0d, a[2][0],a[2][1],a[2][2],a[2][3], b1[0],b1[1]);
            mma_bf16(P1a,P1b,P1c,P1d, a[0][0],a[0][1],a[0][2],a[0][3], b3[2],b3[3]);
            mma_bf16(Q1a,Q1b,Q1c,Q1d, a[2][0],a[2][1],a[2][2],a[2][3], b1[2],b1[3]);

            const int nb0 = ch * CHUNK + no;
            const int nb1 = nb0 + 8;
            float s0 = P0a + Q0a, s1 = P0b + Q0b, s2 = P0c + Q0c, s3 = P0d + Q0d;
            float s4 = P1a + Q1a, s5 = P1b + Q1b, s6 = P1c + Q1c, s7 = P1d + Q1d;
            if (s0 < bv[0]) { bv[0] = s0; bn[0] = nb0; }
            if (s1 < bv[1]) { bv[1] = s1; bn[1] = nb0; }
            if (s2 < bv[2]) { bv[2] = s2; bn[2] = nb0; }
            if (s3 < bv[3]) { bv[3] = s3; bn[3] = nb0; }
            if (s4 < bv[4]) { bv[4] = s4; bn[4] = nb1; }
            if (s5 < bv[5]) { bv[5] = s5; bn[5] = nb1; }
            if (s6 < bv[6]) { bv[6] = s6; bn[6] = nb1; }
            if (s7 < bv[7]) { bv[7] = s7; bn[7] = nb1; }
        }
        __syncthreads();
    }

    // ---- finalize. slot s: rows {r4 (s%4<2? no: slots 0,1=rowA;2,3=rowB)} ----
    // slot -> (row, col): s&1 = col parity, (s>>1)&1 = row half, s>>2 = n-block
    float vA = 3.4e38f, vB = 3.4e38f;
    int iA = 0x7FFFFFFF, iB = 0x7FFFFFFF;
#pragma unroll
    for (int s = 0; s < 8; s++) {
        int idx = bn[s] + kp + (s & 1);
        bool rowB = (s >> 1) & 1;
        if (!rowB) { if (bv[s] < vA || (bv[s] == vA && idx < iA)) { vA = bv[s]; iA = idx; } }
        else       { if (bv[s] < vB || (bv[s] == vB && idx < iB)) { vB = bv[s]; iB = idx; } }
    }
#pragma unroll
    for (int ofs = 1; ofs <= 2; ofs <<= 1) {
        float v = __shfl_xor_sync(0xFFFFFFFFu, vA, ofs);
        int   i = __shfl_xor_sync(0xFFFFFFFFu, iA, ofs);
        if (v < vA || (v == vA && i < iA)) { vA = v; iA = i; }
        v = __shfl_xor_sync(0xFFFFFFFFu, vB, ofs);
        i = __shfl_xor_sync(0xFFFFFFFFu, iB, ofs);
        if (v < vB || (v == vB && i < iB)) { vB = v; iB = i; }
    }

    if ((lane & 3) == 0) {
        out[row0 + r4]     = (float)iA;
        out[row0 + 8 + r4] = (float)iB;
    }
}

// ---------------- launch -----------------------------------------------------
extern "C" void kernel_launch(void* const* d_in, const int* in_sizes, int n_in,
                              void* d_out, int out_size) {
    int a = 0, b = 1, c = 2;
    if (n_in >= 3) {
        if (in_sizes[a] < in_sizes[b]) { int t = a; a = b; b = t; }
        if (in_sizes[b] < in_sizes[c]) { int t = b; b = c; c = t; }
        if (in_sizes[a] < in_sizes[b]) { int t = a; a = b; b = t; }
    }
    const float* x  = (const float*)d_in[a];
    const float* cb = (const float*)d_in[b];
    const float* W  = (const float*)d_in[c];
    float* out = (float*)d_out;

    k_prep<<<KCB / 128, 128>>>(cb);
    k_proj<<<NROWS / 32, 256>>>(x, W);
    k_dist<<<NROWS / 64, 128>>>(out);
}

// round 13
// speedup vs baseline: 1.5858x; 1.3202x over previous
#include <cuda_runtime.h>
#include <cuda_fp16.h>
#include <cstdint>

// Shapes (fixed by reference setup_inputs)
#define NROWS 16384
#define DDIM  512
#define DC    16
#define KCB   8192
#define LN_EPS 1e-5f

// ---------------- device scratch (no allocation allowed) --------------------
// fp16 split-2 of NEGATED LN(h) and of codebook; fp32 half-norms.
__device__ __half g_h1h[NROWS * DC], g_h2h[NROWS * DC];
__device__ __half g_c1h[KCB * DC],   g_c2h[KCB * DC];
__device__ float  g_hc2[KCB];        // 0.5 * sum c^2

// ---------------- helpers ---------------------------------------------------
__device__ __forceinline__ void split2(float v, __half& s1, __half& s2) {
    s1 = __float2half_rn(v);
    s2 = __float2half_rn(v - __half2float(s1));
}
__device__ __forceinline__ uint32_t pack_h2(__half lo, __half hi) {
    uint16_t a = __half_as_ushort(lo), b = __half_as_ushort(hi);
    return (uint32_t)a | ((uint32_t)b << 16);
}

__device__ __forceinline__ void mma_fp16(float& d0, float& d1, float& d2, float& d3,
                                         uint32_t a0, uint32_t a1, uint32_t a2, uint32_t a3,
                                         uint32_t b0, uint32_t b1) {
    asm volatile(
        "mma.sync.aligned.m16n8k16.row.col.f32.f16.f16.f32 "
        "{%0,%1,%2,%3}, {%4,%5,%6,%7}, {%8,%9}, {%0,%1,%2,%3};"
        : "+f"(d0), "+f"(d1), "+f"(d2), "+f"(d3)
        : "r"(a0), "r"(a1), "r"(a2), "r"(a3), "r"(b0), "r"(b1));
}

__device__ __forceinline__ void ldsm_x4(uint32_t& r0, uint32_t& r1,
                                        uint32_t& r2, uint32_t& r3, uint32_t saddr) {
    asm volatile("ldmatrix.sync.aligned.m8n8.x4.shared.b16 {%0,%1,%2,%3}, [%4];"
                 : "=r"(r0), "=r"(r1), "=r"(r2), "=r"(r3) : "r"(saddr));
}

// ---------------- kernel 0: codebook prep (fp16 split-2 + half-norms) -------
__global__ void __launch_bounds__(128) k_prep(const float* __restrict__ cb) {
    int k = blockIdx.x * blockDim.x + threadIdx.x;
    if (k >= KCB) return;
    const float4* c4 = (const float4*)(cb + (size_t)k * DC);
    float4 q0 = c4[0], q1 = c4[1], q2 = c4[2], q3 = c4[3];
    float cv[DC] = {q0.x, q0.y, q0.z, q0.w, q1.x, q1.y, q1.z, q1.w,
                    q2.x, q2.y, q2.z, q2.w, q3.x, q3.y, q3.z, q3.w};
    float c2 = 0.f;
#pragma unroll
    for (int j = 0; j < DC; j++) c2 = fmaf(cv[j], cv[j], c2);
    g_hc2[k] = 0.5f * c2;

    uint32_t p1[8], p2[8];
#pragma unroll
    for (int j = 0; j < 8; j++) {
        __half a1, a2, b1, b2;
        split2(cv[2 * j], a1, a2);
        split2(cv[2 * j + 1], b1, b2);
        p1[j] = pack_h2(a1, b1);
        p2[j] = pack_h2(a2, b2);
    }
    ((uint4*)&g_c1h[k * DC])[0] = *(uint4*)&p1[0];
    ((uint4*)&g_c1h[k * DC])[1] = *(uint4*)&p1[4];
    ((uint4*)&g_c2h[k * DC])[0] = *(uint4*)&p2[0];
    ((uint4*)&g_c2h[k * DC])[1] = *(uint4*)&p2[4];
}

// ---------------- kernel 1: projection + LayerNorm -> split2(-h) ------------
// Warp handles 4 rows; W registers hoisted across rows (20 LDG per 64 FMA).
__global__ void __launch_bounds__(256) k_proj(
    const float* __restrict__ x, const float* __restrict__ W)
{
    const int warp = threadIdx.x >> 5;
    const int lane = threadIdx.x & 31;
    const int rowBase = (blockIdx.x * 8 + warp) * 4;

    float acc[4][DC];
#pragma unroll
    for (int r = 0; r < 4; r++)
#pragma unroll
        for (int j = 0; j < DC; j++) acc[r][j] = 0.f;

#pragma unroll 2
    for (int it = 0; it < DDIM / 32; it++) {
        const int d = it * 32 + lane;
        float wv[DC];
#pragma unroll
        for (int j = 0; j < DC; j++) wv[j] = W[j * DDIM + d];   // L1-hot, hoisted
#pragma unroll
        for (int r = 0; r < 4; r++) {
            float xv = x[(size_t)(rowBase + r) * DDIM + d];     // coalesced
#pragma unroll
            for (int j = 0; j < DC; j++)
                acc[r][j] = fmaf(xv, wv[j], acc[r][j]);
        }
    }

#pragma unroll
    for (int r = 0; r < 4; r++) {
        const int row = rowBase + r;
#pragma unroll
        for (int j = 0; j < DC; j++) {
#pragma unroll
            for (int ofs = 16; ofs > 0; ofs >>= 1)
                acc[r][j] += __shfl_xor_sync(0xFFFFFFFFu, acc[r][j], ofs);
        }

        float s = 0.f;
#pragma unroll
        for (int j = 0; j < DC; j++) s += acc[r][j];
        float mu = s * (1.0f / DC);
        float v = 0.f;
#pragma unroll
        for (int j = 0; j < DC; j++) { float d = acc[r][j] - mu; v = fmaf(d, d, v); }
        float denom = sqrtf(v * (1.0f / DC) + LN_EPS);

        if (lane < 8) {
            float e0 = (mu - acc[r][2 * lane]) / denom;        // negated h
            float e1 = (mu - acc[r][2 * lane + 1]) / denom;
            __half a1, a2, b1, b2;
            split2(e0, a1, a2);
            split2(e1, b1, b2);
            ((uint32_t*)&g_h1h[row * DC])[lane] = pack_h2(a1, b1);
            ((uint32_t*)&g_h2h[row * DC])[lane] = pack_h2(a2, b2);
        }
    }
}

// ---------------- kernel 2: tensor-core distance + argmin -------------------
// 256 blocks x 128 threads (4 warps). Warp owns 16 rows. 16 codes / iteration;
// 6 MMAs in 2 independent 3-deep chains, D seeded with 0.5||c||^2.
#define CHUNK 128
__global__ void __launch_bounds__(128) k_dist(float* __restrict__ out) {
    __shared__ __half smC[2][2][CHUNK * DC];   // 16 KB
    __shared__ float  smH[2][CHUNK];           // 1 KB

    const int tid  = threadIdx.x;
    const int warp = tid >> 5;
    const int lane = tid & 31;
    const int row0 = blockIdx.x * 64 + warp * 16;
    const int r4   = lane >> 2;
    const int kp   = (lane & 3) * 2;

    // loop-invariant A fragments (layout validated in R10/R11)
    uint32_t a1[4], a2[4];
    {
        a1[0] = *(const uint32_t*)&g_h1h[(row0 + r4) * DC + kp];
        a1[1] = *(const uint32_t*)&g_h1h[(row0 + 8 + r4) * DC + kp];
        a1[2] = *(const uint32_t*)&g_h1h[(row0 + r4) * DC + kp + 8];
        a1[3] = *(const uint32_t*)&g_h1h[(row0 + 8 + r4) * DC + kp + 8];
        a2[0] = *(const uint32_t*)&g_h2h[(row0 + r4) * DC + kp];
        a2[1] = *(const uint32_t*)&g_h2h[(row0 + 8 + r4) * DC + kp];
        a2[2] = *(const uint32_t*)&g_h2h[(row0 + r4) * DC + kp + 8];
        a2[3] = *(const uint32_t*)&g_h2h[(row0 + 8 + r4) * DC + kp + 8];
    }

    auto stage = [&](int ch, int buf) {
        const uint4* s1 = ((const uint4*)g_c1h) + ch * 256;   // 4KB = 256 uint4
        const uint4* s2 = ((const uint4*)g_c2h) + ch * 256;
        ((uint4*)smC[buf][0])[tid]       = s1[tid];
        ((uint4*)smC[buf][0])[tid + 128] = s1[tid + 128];
        ((uint4*)smC[buf][1])[tid]       = s2[tid];
        ((uint4*)smC[buf][1])[tid + 128] = s2[tid + 128];
        if (tid < 32) ((uint4*)smH[buf])[tid] = ((const uint4*)(g_hc2 + ch * CHUNK))[tid];
    };

    // ldmatrix.x4 lane mapping: two n8 blocks x two k-halves
    const int coderow = (lane & 7) + ((lane & 16) >> 1);  // 0..15
    const int khalf   = (lane >> 3) & 1;
    const uint32_t lmoff = (uint32_t)(coderow * 32 + khalf * 16);  // bytes

    float bv[8];
    int   bn[8];
#pragma unroll
    for (int s = 0; s < 8; s++) { bv[s] = 3.4e38f; bn[s] = 0; }

    stage(0, 0);
    __syncthreads();

    for (int ch = 0; ch < KCB / CHUNK; ch++) {
        const int buf = ch & 1;
        if (ch + 1 < KCB / CHUNK) stage(ch + 1, buf ^ 1);

        const uint32_t sb1 = (uint32_t)__cvta_generic_to_shared(&smC[buf][0][0]) + lmoff;
        const uint32_t sb2 = (uint32_t)__cvta_generic_to_shared(&smC[buf][1][0]) + lmoff;

#pragma unroll 2
        for (int no = 0; no < CHUNK; no += 16) {
            uint32_t b1[4], b2[4];
            ldsm_x4(b1[0], b1[1], b1[2], b1[3], sb1 + no * 32);
            ldsm_x4(b2[0], b2[1], b2[2], b2[3], sb2 + no * 32);

            float2 h0 = *(const float2*)&smH[buf][no + kp];
            float2 h1 = *(const float2*)&smH[buf][no + 8 + kp];

            // block0 / block1: single accumulator each, seeded 0.5||c||^2,
            // 3-term fp16 split: a1*b1 + a1*b2 + a2*b1  (h2*c2 ~ 2^-24 dropped)
            float D0a = h0.x, D0b = h0.y, D0c = h0.x, D0d = h0.y;
            float D1a = h1.x, D1b = h1.y, D1c = h1.x, D1d = h1.y;

            mma_fp16(D0a,D0b,D0c,D0d, a1[0],a1[1],a1[2],a1[3], b1[0],b1[1]);
            mma_fp16(D1a,D1b,D1c,D1d, a1[0],a1[1],a1[2],a1[3], b1[2],b1[3]);
            mma_fp16(D0a,D0b,D0c,D0d, a1[0],a1[1],a1[2],a1[3], b2[0],b2[1]);
            mma_fp16(D1a,D1b,D1c,D1d, a1[0],a1[1],a1[2],a1[3], b2[2],b2[3]);
            mma_fp16(D0a,D0b,D0c,D0d, a2[0],a2[1],a2[2],a2[3], b1[0],b1[1]);
            mma_fp16(D1a,D1b,D1c,D1d, a2[0],a2[1],a2[2],a2[3], b1[2],b1[3]);

            const int nb0 = ch * CHUNK + no;
            const int nb1 = nb0 + 8;
            if (D0a < bv[0]) { bv[0] = D0a; bn[0] = nb0; }
            if (D0b < bv[1]) { bv[1] = D0b; bn[1] = nb0; }
            if (D0c < bv[2]) { bv[2] = D0c; bn[2] = nb0; }
            if (D0d < bv[3]) { bv[3] = D0d; bn[3] = nb0; }
            if (D1a < bv[4]) { bv[4] = D1a; bn[4] = nb1; }
            if (D1b < bv[5]) { bv[5] = D1b; bn[5] = nb1; }
            if (D1c < bv[6]) { bv[6] = D1c; bn[6] = nb1; }
            if (D1d < bv[7]) { bv[7] = D1d; bn[7] = nb1; }
        }
        __syncthreads();
    }

    // ---- finalize: slot -> (row half, col parity), merge cols then quads ----
    float vA = 3.4e38f, vB = 3.4e38f;
    int iA = 0x7FFFFFFF, iB = 0x7FFFFFFF;
#pragma unroll
    for (int s = 0; s < 8; s++) {
        int idx = bn[s] + kp + (s & 1);
        bool rowB = (s >> 1) & 1;
        if (!rowB) { if (bv[s] < vA || (bv[s] == vA && idx < iA)) { vA = bv[s]; iA = idx; } }
        else       { if (bv[s] < vB || (bv[s] == vB && idx < iB)) { vB = bv[s]; iB = idx; } }
    }
#pragma unroll
    for (int ofs = 1; ofs <= 2; ofs <<= 1) {
        float v = __shfl_xor_sync(0xFFFFFFFFu, vA, ofs);
        int   i = __shfl_xor_sync(0xFFFFFFFFu, iA, ofs);
        if (v < vA || (v == vA && i < iA)) { vA = v; iA = i; }
        v = __shfl_xor_sync(0xFFFFFFFFu, vB, ofs);
        i = __shfl_xor_sync(0xFFFFFFFFu, iB, ofs);
        if (v < vB || (v == vB && i < iB)) { vB = v; iB = i; }
    }

    if ((lane & 3) == 0) {
        out[row0 + r4]     = (float)iA;
        out[row0 + 8 + r4] = (float)iB;
    }
}

// ---------------- launch -----------------------------------------------------
extern "C" void kernel_launch(void* const* d_in, const int* in_sizes, int n_in,
                              void* d_out, int out_size) {
    int a = 0, b = 1, c = 2;
    if (n_in >= 3) {
        if (in_sizes[a] < in_sizes[b]) { int t = a; a = b; b = t; }
        if (in_sizes[b] < in_sizes[c]) { int t = b; b = c; c = t; }
        if (in_sizes[a] < in_sizes[b]) { int t = a; a = b; b = t; }
    }
    const float* x  = (const float*)d_in[a];
    const float* cb = (const float*)d_in[b];
    const float* W  = (const float*)d_in[c];
    float* out = (float*)d_out;

    k_prep<<<KCB / 128, 128>>>(cb);
    k_proj<<<NROWS / 32, 256>>>(x, W);
    k_dist<<<NROWS / 64, 128>>>(out);
}

// round 14
// speedup vs baseline: 1.8893x; 1.1914x over previous
#include <cuda_runtime.h>
#include <cuda_fp16.h>
#include <cstdint>

// Shapes (fixed by reference setup_inputs)
#define NROWS 16384
#define DDIM  512
#define DC    16
#define KCB   8192
#define LN_EPS 1e-5f

// ---------------- device scratch (no allocation allowed) --------------------
__device__ __half g_h1h[NROWS * DC], g_h2h[NROWS * DC];
__device__ __half g_c1h[KCB * DC],   g_c2h[KCB * DC];
__device__ float  g_hc2[KCB];        // 0.5 * sum c^2

// ---------------- helpers ---------------------------------------------------
__device__ __forceinline__ void split2(float v, __half& s1, __half& s2) {
    s1 = __float2half_rn(v);
    s2 = __float2half_rn(v - __half2float(s1));
}
__device__ __forceinline__ uint32_t pack_h2(__half lo, __half hi) {
    uint16_t a = __half_as_ushort(lo), b = __half_as_ushort(hi);
    return (uint32_t)a | ((uint32_t)b << 16);
}

__device__ __forceinline__ void mma_fp16(float& d0, float& d1, float& d2, float& d3,
                                         uint32_t a0, uint32_t a1, uint32_t a2, uint32_t a3,
                                         uint32_t b0, uint32_t b1) {
    asm volatile(
        "mma.sync.aligned.m16n8k16.row.col.f32.f16.f16.f32 "
        "{%0,%1,%2,%3}, {%4,%5,%6,%7}, {%8,%9}, {%0,%1,%2,%3};"
        : "+f"(d0), "+f"(d1), "+f"(d2), "+f"(d3)
        : "r"(a0), "r"(a1), "r"(a2), "r"(a3), "r"(b0), "r"(b1));
}

__device__ __forceinline__ void ldsm_x4(uint32_t& r0, uint32_t& r1,
                                        uint32_t& r2, uint32_t& r3, uint32_t saddr) {
    asm volatile("ldmatrix.sync.aligned.m8n8.x4.shared.b16 {%0,%1,%2,%3}, [%4];"
                 : "=r"(r0), "=r"(r1), "=r"(r2), "=r"(r3) : "r"(saddr));
}

// ---------------- kernel 0: codebook prep (fp16 split-2 + half-norms) -------
__global__ void __launch_bounds__(128) k_prep(const float* __restrict__ cb) {
    int k = blockIdx.x * blockDim.x + threadIdx.x;
    if (k >= KCB) return;
    const float4* c4 = (const float4*)(cb + (size_t)k * DC);
    float4 q0 = c4[0], q1 = c4[1], q2 = c4[2], q3 = c4[3];
    float cv[DC] = {q0.x, q0.y, q0.z, q0.w, q1.x, q1.y, q1.z, q1.w,
                    q2.x, q2.y, q2.z, q2.w, q3.x, q3.y, q3.z, q3.w};
    float c2 = 0.f;
#pragma unroll
    for (int j = 0; j < DC; j++) c2 = fmaf(cv[j], cv[j], c2);
    g_hc2[k] = 0.5f * c2;

    uint32_t p1[8], p2[8];
#pragma unroll
    for (int j = 0; j < 8; j++) {
        __half a1, a2, b1, b2;
        split2(cv[2 * j], a1, a2);
        split2(cv[2 * j + 1], b1, b2);
        p1[j] = pack_h2(a1, b1);
        p2[j] = pack_h2(a2, b2);
    }
    ((uint4*)&g_c1h[k * DC])[0] = *(uint4*)&p1[0];
    ((uint4*)&g_c1h[k * DC])[1] = *(uint4*)&p1[4];
    ((uint4*)&g_c2h[k * DC])[0] = *(uint4*)&p2[0];
    ((uint4*)&g_c2h[k * DC])[1] = *(uint4*)&p2[4];
}

// ---------------- kernel 1: projection + LayerNorm -> split2(-h) ------------
__global__ void __launch_bounds__(256) k_proj(
    const float* __restrict__ x, const float* __restrict__ W)
{
    const int warp = threadIdx.x >> 5;
    const int lane = threadIdx.x & 31;
    const int rowBase = (blockIdx.x * 8 + warp) * 4;

    float acc[4][DC];
#pragma unroll
    for (int r = 0; r < 4; r++)
#pragma unroll
        for (int j = 0; j < DC; j++) acc[r][j] = 0.f;

#pragma unroll 2
    for (int it = 0; it < DDIM / 32; it++) {
        const int d = it * 32 + lane;
        float wv[DC];
#pragma unroll
        for (int j = 0; j < DC; j++) wv[j] = W[j * DDIM + d];
#pragma unroll
        for (int r = 0; r < 4; r++) {
            float xv = x[(size_t)(rowBase + r) * DDIM + d];
#pragma unroll
            for (int j = 0; j < DC; j++)
                acc[r][j] = fmaf(xv, wv[j], acc[r][j]);
        }
    }

#pragma unroll
    for (int r = 0; r < 4; r++) {
        const int row = rowBase + r;
#pragma unroll
        for (int j = 0; j < DC; j++) {
#pragma unroll
            for (int ofs = 16; ofs > 0; ofs >>= 1)
                acc[r][j] += __shfl_xor_sync(0xFFFFFFFFu, acc[r][j], ofs);
        }

        float s = 0.f;
#pragma unroll
        for (int j = 0; j < DC; j++) s += acc[r][j];
        float mu = s * (1.0f / DC);
        float v = 0.f;
#pragma unroll
        for (int j = 0; j < DC; j++) { float d = acc[r][j] - mu; v = fmaf(d, d, v); }
        float denom = sqrtf(v * (1.0f / DC) + LN_EPS);

        if (lane < 8) {
            float e0 = (mu - acc[r][2 * lane]) / denom;
            float e1 = (mu - acc[r][2 * lane + 1]) / denom;
            __half a1, a2, b1, b2;
            split2(e0, a1, a2);
            split2(e1, b1, b2);
            ((uint32_t*)&g_h1h[row * DC])[lane] = pack_h2(a1, b1);
            ((uint32_t*)&g_h2h[row * DC])[lane] = pack_h2(a2, b2);
        }
    }
}

// ---------------- kernel 2: tensor-core distance + argmin (split-K groups) --
// 256 blocks x 256 threads (8 warps = 2 groups of 4). Block owns 64 rows.
// Group 0 scans even 128-code chunks, group 1 odd; merge at the end.
#define CHUNK 128
__global__ void __launch_bounds__(256) k_dist(float* __restrict__ out) {
    __shared__ __half smC[2][2][2][CHUNK * DC];  // [group][buf][split] = 32 KB
    __shared__ float  smH[2][2][CHUNK];          // 2 KB
    __shared__ float  mv[64];
    __shared__ int    mi[64];

    const int tid    = threadIdx.x;
    const int warp   = tid >> 5;
    const int lane   = tid & 31;
    const int gid    = warp >> 2;        // 0 or 1
    const int w4     = warp & 3;
    const int tid128 = tid & 127;
    const int row0   = blockIdx.x * 64 + w4 * 16;
    const int r4     = lane >> 2;
    const int kp     = (lane & 3) * 2;

    // loop-invariant A fragments (layout validated R10-R13)
    uint32_t a1[4], a2[4];
    a1[0] = *(const uint32_t*)&g_h1h[(row0 + r4) * DC + kp];
    a1[1] = *(const uint32_t*)&g_h1h[(row0 + 8 + r4) * DC + kp];
    a1[2] = *(const uint32_t*)&g_h1h[(row0 + r4) * DC + kp + 8];
    a1[3] = *(const uint32_t*)&g_h1h[(row0 + 8 + r4) * DC + kp + 8];
    a2[0] = *(const uint32_t*)&g_h2h[(row0 + r4) * DC + kp];
    a2[1] = *(const uint32_t*)&g_h2h[(row0 + 8 + r4) * DC + kp];
    a2[2] = *(const uint32_t*)&g_h2h[(row0 + r4) * DC + kp + 8];
    a2[3] = *(const uint32_t*)&g_h2h[(row0 + 8 + r4) * DC + kp + 8];

    auto stage = [&](int ch, int buf) {     // ch = global chunk index
        const uint4* s1 = ((const uint4*)g_c1h) + ch * 256;
        const uint4* s2 = ((const uint4*)g_c2h) + ch * 256;
        ((uint4*)smC[gid][buf][0])[tid128]       = s1[tid128];
        ((uint4*)smC[gid][buf][0])[tid128 + 128] = s1[tid128 + 128];
        ((uint4*)smC[gid][buf][1])[tid128]       = s2[tid128];
        ((uint4*)smC[gid][buf][1])[tid128 + 128] = s2[tid128 + 128];
        if (tid128 < 32)
            ((uint4*)smH[gid][buf])[tid128] = ((const uint4*)(g_hc2 + ch * CHUNK))[tid128];
    };
    auto gbar = [&]() {   // named barrier per 128-thread group
        asm volatile("bar.sync %0, 128;" :: "r"(gid + 1) : "memory");
    };

    const int coderow = (lane & 7) + ((lane & 16) >> 1);
    const int khalf   = (lane >> 3) & 1;
    const uint32_t lmoff = (uint32_t)(coderow * 32 + khalf * 16);

    float bv[8];
    int   bn[8];
#pragma unroll
    for (int s = 0; s < 8; s++) { bv[s] = 3.4e38f; bn[s] = 0; }

    stage(gid, 0);
    gbar();

    const int NT = (KCB / CHUNK) / 2;   // 32 chunks per group
    for (int t = 0; t < NT; t++) {
        const int ch  = 2 * t + gid;
        const int buf = t & 1;
        if (t + 1 < NT) stage(2 * (t + 1) + gid, buf ^ 1);

        const uint32_t sb1 = (uint32_t)__cvta_generic_to_shared(&smC[gid][buf][0][0]) + lmoff;
        const uint32_t sb2 = (uint32_t)__cvta_generic_to_shared(&smC[gid][buf][1][0]) + lmoff;

#pragma unroll 2
        for (int no = 0; no < CHUNK; no += 16) {
            uint32_t b1[4], b2[4];
            ldsm_x4(b1[0], b1[1], b1[2], b1[3], sb1 + no * 32);
            ldsm_x4(b2[0], b2[1], b2[2], b2[3], sb2 + no * 32);

            float2 h0 = *(const float2*)&smH[gid][buf][no + kp];
            float2 h1 = *(const float2*)&smH[gid][buf][no + 8 + kp];

            float D0a = h0.x, D0b = h0.y, D0c = h0.x, D0d = h0.y;
            float D1a = h1.x, D1b = h1.y, D1c = h1.x, D1d = h1.y;

            mma_fp16(D0a,D0b,D0c,D0d, a1[0],a1[1],a1[2],a1[3], b1[0],b1[1]);
            mma_fp16(D1a,D1b,D1c,D1d, a1[0],a1[1],a1[2],a1[3], b1[2],b1[3]);
            mma_fp16(D0a,D0b,D0c,D0d, a1[0],a1[1],a1[2],a1[3], b2[0],b2[1]);
            mma_fp16(D1a,D1b,D1c,D1d, a1[0],a1[1],a1[2],a1[3], b2[2],b2[3]);
            mma_fp16(D0a,D0b,D0c,D0d, a2[0],a2[1],a2[2],a2[3], b1[0],b1[1]);
            mma_fp16(D1a,D1b,D1c,D1d, a2[0],a2[1],a2[2],a2[3], b1[2],b1[3]);

            const int nb0 = ch * CHUNK + no;
            const int nb1 = nb0 + 8;
            if (D0a < bv[0]) { bv[0] = D0a; bn[0] = nb0; }
            if (D0b < bv[1]) { bv[1] = D0b; bn[1] = nb0; }
            if (D0c < bv[2]) { bv[2] = D0c; bn[2] = nb0; }
            if (D0d < bv[3]) { bv[3] = D0d; bn[3] = nb0; }
            if (D1a < bv[4]) { bv[4] = D1a; bn[4] = nb1; }
            if (D1b < bv[5]) { bv[5] = D1b; bn[5] = nb1; }
            if (D1c < bv[6]) { bv[6] = D1c; bn[6] = nb1; }
            if (D1d < bv[7]) { bv[7] = D1d; bn[7] = nb1; }
        }
        gbar();
    }

    // ---- in-warp merge (as R13): per writer lane, rows r4 and 8+r4 ----
    float vA = 3.4e38f, vB = 3.4e38f;
    int iA = 0x7FFFFFFF, iB = 0x7FFFFFFF;
#pragma unroll
    for (int s = 0; s < 8; s++) {
        int idx = bn[s] + kp + (s & 1);
        bool rowB = (s >> 1) & 1;
        if (!rowB) { if (bv[s] < vA || (bv[s] == vA && idx < iA)) { vA = bv[s]; iA = idx; } }
        else       { if (bv[s] < vB || (bv[s] == vB && idx < iB)) { vB = bv[s]; iB = idx; } }
    }
#pragma unroll
    for (int ofs = 1; ofs <= 2; ofs <<= 1) {
        float v = __shfl_xor_sync(0xFFFFFFFFu, vA, ofs);
        int   i = __shfl_xor_sync(0xFFFFFFFFu, iA, ofs);
        if (v < vA || (v == vA && i < iA)) { vA = v; iA = i; }
        v = __shfl_xor_sync(0xFFFFFFFFu, vB, ofs);
        i = __shfl_xor_sync(0xFFFFFFFFu, iB, ofs);
        if (v < vB || (v == vB && i < iB)) { vB = v; iB = i; }
    }

    // ---- cross-group merge via smem (scores bit-identical across groups) ---
    const int lrowA = w4 * 16 + r4;
    const int lrowB = lrowA + 8;
    if (gid == 0 && (lane & 3) == 0) {
        mv[lrowA] = vA; mi[lrowA] = iA;
        mv[lrowB] = vB; mi[lrowB] = iB;
    }
    __syncthreads();
    if (gid == 1 && (lane & 3) == 0) {
        float v0 = mv[lrowA]; int i0 = mi[lrowA];
        if (v0 < vA || (v0 == vA && i0 < iA)) { vA = v0; iA = i0; }
        float v1 = mv[lrowB]; int i1 = mi[lrowB];
        if (v1 < vB || (v1 == vB && i1 < iB)) { vB = v1; iB = i1; }
        out[blockIdx.x * 64 + lrowA] = (float)iA;
        out[blockIdx.x * 64 + lrowB] = (float)iB;
    }
}

// ---------------- launch -----------------------------------------------------
extern "C" void kernel_launch(void* const* d_in, const int* in_sizes, int n_in,
                              void* d_out, int out_size) {
    int a = 0, b = 1, c = 2;
    if (n_in >= 3) {
        if (in_sizes[a] < in_sizes[b]) { int t = a; a = b; b = t; }
        if (in_sizes[b] < in_sizes[c]) { int t = b; b = c; c = t; }
        if (in_sizes[a] < in_sizes[b]) { int t = a; a = b; b = t; }
    }
    const float* x  = (const float*)d_in[a];
    const float* cb = (const float*)d_in[b];
    const float* W  = (const float*)d_in[c];
    float* out = (float*)d_out;

    k_prep<<<KCB / 128, 128>>>(cb);
    k_proj<<<NROWS / 32, 256>>>(x, W);
    k_dist<<<NROWS / 64, 256>>>(out);
}